// round 16
// baseline (speedup 1.0000x reference)
#include <cuda_runtime.h>
#include <math.h>

#define NN   262144
#define DIMM 256
#define NH   4
#define HD   64
#define BSEG 4096
#define SCALE 0.125f
#define EPSV 1e-8f
#define RG   6      // k_main ring slots per warp (slot = 2 rows = 2KB); prefetch 5

// ---- device scratch ----
__device__ float g_wtil[NH * DIMM];
__device__ float g_ctil[NH];
__device__ int   g_segstart[BSEG + 1];
__device__ float g_t[BSEG * NH * DIMM];      // normalized weighted sums t~
__device__ float g_coef[BSEG * NH];          // esum/(esum+eps)
__device__ float g_wt[NH * 64 * 64 * 4];     // vw transposed: [h][j4][d][jj]

// ---- packed f32x2 helpers ----
__device__ __forceinline__ unsigned long long f2mul(unsigned long long a, unsigned long long b) {
    unsigned long long r; asm("mul.rn.f32x2 %0,%1,%2;" : "=l"(r) : "l"(a), "l"(b)); return r;
}
__device__ __forceinline__ unsigned long long f2fma(unsigned long long a, unsigned long long b,
                                                    unsigned long long c) {
    unsigned long long r; asm("fma.rn.f32x2 %0,%1,%2,%3;" : "=l"(r) : "l"(a), "l"(b), "l"(c)); return r;
}
__device__ __forceinline__ unsigned long long fpack(float a, float b) {
    unsigned long long r; asm("mov.b64 %0,{%1,%2};" : "=l"(r) : "f"(a), "f"(b)); return r;
}
__device__ __forceinline__ float f2lo(unsigned long long a) { float2 p = *(float2*)&a; return p.x; }
__device__ __forceinline__ float f2hi(unsigned long long a) { float2 p = *(float2*)&a; return p.y; }

__device__ __forceinline__ void cpa16(void* dst_smem, const void* src) {
    unsigned u = (unsigned)__cvta_generic_to_shared(dst_smem);
    asm volatile("cp.async.cg.shared.global [%0], [%1], 16;" :: "r"(u), "l"(src) : "memory");
}
#define CP_COMMIT() asm volatile("cp.async.commit_group;" ::: "memory")
#define CP_WAIT(n)  asm volatile("cp.async.wait_group %0;" :: "n"(n) : "memory")

// ---------------------------------------------------------------------------
// k_prep: ONE launch. Blocks [0,1024): segment boundaries; block 1024: fold
// key weights; blocks [1025,1281): transpose vw. Bodies verbatim from R14.
// ---------------------------------------------------------------------------
__global__ void k_prep(const int* __restrict__ batch,
                       const float* __restrict__ q,
                       const float* __restrict__ kw,
                       const float* __restrict__ kb,
                       const float* __restrict__ vw) {
    const int bx = blockIdx.x;
    if (bx < NN / 256) {
        int i = bx * 256 + threadIdx.x;
        int cur  = batch[i];
        int prev = (i == 0) ? -1 : batch[i - 1];
        for (int b = prev + 1; b <= cur; b++) g_segstart[b] = i;
        if (i == NN - 1)
            for (int b = cur + 1; b <= BSEG; b++) g_segstart[b] = NN;
    } else if (bx == NN / 256) {
        int j = threadIdx.x;
#pragma unroll
        for (int h = 0; h < NH; h++) {
            float acc = 0.f;
#pragma unroll 8
            for (int d = 0; d < HD; d++)
                acc = fmaf(q[h * HD + d], kw[(h * HD + d) * DIMM + j], acc);
            g_wtil[h * DIMM + j] = acc * SCALE;
        }
        if (j == 0) {
#pragma unroll
            for (int h = 0; h < NH; h++) {
                float c = 0.f;
#pragma unroll 8
                for (int d = 0; d < HD; d++)
                    c = fmaf(q[h * HD + d], kb[h * HD + d], c);
                g_ctil[h] = c * SCALE;
            }
        }
    } else {
        int i = (bx - NN / 256 - 1) * 256 + threadIdx.x;
        int row = i >> 8, j = i & 255;
        int h = row >> 6, d = row & 63;
        g_wt[((h * 64 + (j >> 2)) * 64 + d) * 4 + (j & 3)] = vw[i];
    }
}

// ---------------------------------------------------------------------------
// k_main: R14 body VERBATIM (weights in registers, regs~114, measured 52.9us
// at DRAM=67%), with ring deepened RG 4->6 / prefetch 3->5 (zero extra regs
// or hot-loop instructions; in-flight 6KB -> 10KB per warp).
// ---------------------------------------------------------------------------
__device__ __forceinline__ void process_pair(
    ulonglong2 v0, ulonglong2 v1, ulonglong2 u0, ulonglong2 u1,
    bool row1ok, int lane, float ctv,
    const ulonglong2 (&w0)[NH], const ulonglong2 (&w1)[NH],
    ulonglong2 (&accA)[NH], ulonglong2 (&accB)[NH], float& es)
{
    float a[8];
#pragma unroll
    for (int h = 0; h < NH; h++) {
        unsigned long long p;
        p = f2mul(v0.x, w0[h].x); p = f2fma(v0.y, w0[h].y, p);
        p = f2fma(v1.x, w1[h].x, p); p = f2fma(v1.y, w1[h].y, p);
        a[h] = f2lo(p) + f2hi(p);
        p = f2mul(u0.x, w0[h].x); p = f2fma(u0.y, w0[h].y, p);
        p = f2fma(u1.x, w1[h].x, p); p = f2fma(u1.y, w1[h].y, p);
        a[4 + h] = f2lo(p) + f2hi(p);
    }
    const bool b4 = (lane & 16) != 0;
#pragma unroll
    for (int i = 0; i < 4; i++) {
        float mine = b4 ? a[i + 4] : a[i];
        float oth  = b4 ? a[i]     : a[i + 4];
        oth = __shfl_xor_sync(0xffffffffu, oth, 16);
        a[i] = mine + oth;
    }
    const bool b3 = (lane & 8) != 0;
#pragma unroll
    for (int i = 0; i < 2; i++) {
        float mine = b3 ? a[i + 2] : a[i];
        float oth  = b3 ? a[i]     : a[i + 2];
        oth = __shfl_xor_sync(0xffffffffu, oth, 8);
        a[i] = mine + oth;
    }
    const bool b2 = (lane & 4) != 0;
    float mine = b2 ? a[1] : a[0];
    float oth  = b2 ? a[0] : a[1];
    oth = __shfl_xor_sync(0xffffffffu, oth, 4);
    float c = mine + oth;
    c += __shfl_xor_sync(0xffffffffu, c, 2);
    c += __shfl_xor_sync(0xffffffffu, c, 1);

    float e = __expf(c + ctv);            // lane's item: r=(lane>>4)&1, h=(lane>>2)&3
    if (lane >= 16 && !row1ok) e = 0.f;   // zero padded row
    if ((lane & 3) == 0) es += e;         // one accumulator lane per item

    float e00 = __shfl_sync(0xffffffffu, e, 0);
    float e01 = __shfl_sync(0xffffffffu, e, 4);
    float e02 = __shfl_sync(0xffffffffu, e, 8);
    float e03 = __shfl_sync(0xffffffffu, e, 12);
    float e10 = __shfl_sync(0xffffffffu, e, 16);
    float e11 = __shfl_sync(0xffffffffu, e, 20);
    float e12 = __shfl_sync(0xffffffffu, e, 24);
    float e13 = __shfl_sync(0xffffffffu, e, 28);

    unsigned long long k0 = fpack(e00, e00), k1 = fpack(e01, e01);
    unsigned long long k2 = fpack(e02, e02), k3 = fpack(e03, e03);
    unsigned long long m0 = fpack(e10, e10), m1 = fpack(e11, e11);
    unsigned long long m2 = fpack(e12, e12), m3 = fpack(e13, e13);

    accA[0].x = f2fma(k0, v0.x, accA[0].x); accA[0].y = f2fma(k0, v0.y, accA[0].y);
    accB[0].x = f2fma(k0, v1.x, accB[0].x); accB[0].y = f2fma(k0, v1.y, accB[0].y);
    accA[1].x = f2fma(k1, v0.x, accA[1].x); accA[1].y = f2fma(k1, v0.y, accA[1].y);
    accB[1].x = f2fma(k1, v1.x, accB[1].x); accB[1].y = f2fma(k1, v1.y, accB[1].y);
    accA[2].x = f2fma(k2, v0.x, accA[2].x); accA[2].y = f2fma(k2, v0.y, accA[2].y);
    accB[2].x = f2fma(k2, v1.x, accB[2].x); accB[2].y = f2fma(k2, v1.y, accB[2].y);
    accA[3].x = f2fma(k3, v0.x, accA[3].x); accA[3].y = f2fma(k3, v0.y, accA[3].y);
    accB[3].x = f2fma(k3, v1.x, accB[3].x); accB[3].y = f2fma(k3, v1.y, accB[3].y);

    accA[0].x = f2fma(m0, u0.x, accA[0].x); accA[0].y = f2fma(m0, u0.y, accA[0].y);
    accB[0].x = f2fma(m0, u1.x, accB[0].x); accB[0].y = f2fma(m0, u1.y, accB[0].y);
    accA[1].x = f2fma(m1, u0.x, accA[1].x); accA[1].y = f2fma(m1, u0.y, accA[1].y);
    accB[1].x = f2fma(m1, u1.x, accB[1].x); accB[1].y = f2fma(m1, u1.y, accB[1].y);
    accA[2].x = f2fma(m2, u0.x, accA[2].x); accA[2].y = f2fma(m2, u0.y, accA[2].y);
    accB[2].x = f2fma(m2, u1.x, accB[2].x); accB[2].y = f2fma(m2, u1.y, accB[2].y);
    accA[3].x = f2fma(m3, u0.x, accA[3].x); accA[3].y = f2fma(m3, u0.y, accA[3].y);
    accB[3].x = f2fma(m3, u1.x, accB[3].x); accB[3].y = f2fma(m3, u1.y, accB[3].y);
}

__global__ void __launch_bounds__(256) k_main(const float* __restrict__ x) {
    extern __shared__ float4 ring_all[];
    const int lane = threadIdx.x & 31;
    const int wid  = threadIdx.x >> 5;
    const int b    = blockIdx.x * 8 + wid;
    float4* ring = ring_all + wid * (RG * 128);

    const int s0  = g_segstart[b];
    const int s1  = g_segstart[b + 1];
    const int cnt = s1 - s0;
    const int ng  = (cnt + 1) >> 1;

    const float4* wt4 = (const float4*)g_wtil;
    ulonglong2 w0[NH], w1[NH];
#pragma unroll
    for (int h = 0; h < NH; h++) {
        float4 t = wt4[h * 64 + lane];      w0[h] = *(ulonglong2*)&t;
        float4 u = wt4[h * 64 + 32 + lane]; w1[h] = *(ulonglong2*)&u;
    }
    const float ctv = g_ctil[(lane >> 2) & 3];

    ulonglong2 accA[NH], accB[NH];
#pragma unroll
    for (int h = 0; h < NH; h++) { accA[h].x = accA[h].y = 0ull; accB[h].x = accB[h].y = 0ull; }
    float es = 0.f;

    const float4* xp = (const float4*)x;

#define ISSUE(G) do {                                             \
        int slot_ = (G) % RG;                                     \
        int r0_ = s0 + 2 * (G);                                   \
        int r1_ = (2 * (G) + 1 < cnt) ? r0_ + 1 : r0_;            \
        float4* d_ = ring + slot_ * 128;                          \
        cpa16(d_ + lane,      xp + (size_t)r0_ * 64 + lane);      \
        cpa16(d_ + 32 + lane, xp + (size_t)r0_ * 64 + 32 + lane); \
        cpa16(d_ + 64 + lane, xp + (size_t)r1_ * 64 + lane);      \
        cpa16(d_ + 96 + lane, xp + (size_t)r1_ * 64 + 32 + lane); \
    } while (0)

#pragma unroll
    for (int p = 0; p < 5; p++) { if (p < ng) ISSUE(p); CP_COMMIT(); }

    for (int g = 0; g < ng; g++) {
        if (g + 5 < ng) ISSUE(g + 5);
        CP_COMMIT();
        CP_WAIT(5);
        const float4* sl = ring + (g % RG) * 128;
        float4 f0 = sl[lane], f1 = sl[32 + lane];
        float4 f2v = sl[64 + lane], f3 = sl[96 + lane];
        process_pair(*(ulonglong2*)&f0, *(ulonglong2*)&f1,
                     *(ulonglong2*)&f2v, *(ulonglong2*)&f3,
                     (2 * g + 1) < cnt, lane, ctv, w0, w1, accA, accB, es);
    }
#undef ISSUE

    // es: lane 4h (r0) + lane 4h+16 (r1) -> esum[h] at lane 4h
    es += __shfl_xor_sync(0xffffffffu, es, 16);
    float es0 = __shfl_sync(0xffffffffu, es, 0);
    float es1 = __shfl_sync(0xffffffffu, es, 4);
    float es2 = __shfl_sync(0xffffffffu, es, 8);
    float es3 = __shfl_sync(0xffffffffu, es, 12);

    float iv0 = 1.0f / (es0 + EPSV), iv1 = 1.0f / (es1 + EPSV);
    float iv2 = 1.0f / (es2 + EPSV), iv3 = 1.0f / (es3 + EPSV);
    unsigned long long ii[NH] = { fpack(iv0, iv0), fpack(iv1, iv1),
                                  fpack(iv2, iv2), fpack(iv3, iv3) };
    float4* tp = (float4*)(g_t + (size_t)b * NH * DIMM);
#pragma unroll
    for (int h = 0; h < NH; h++) {
        ulonglong2 sa, sb;
        sa.x = f2mul(ii[h], accA[h].x); sa.y = f2mul(ii[h], accA[h].y);
        sb.x = f2mul(ii[h], accB[h].x); sb.y = f2mul(ii[h], accB[h].y);
        tp[h * 64 + lane]      = *(float4*)&sa;
        tp[h * 64 + 32 + lane] = *(float4*)&sb;
    }
    if (lane < NH) {
        float cf = (lane == 0) ? es0 * iv0 : (lane == 1) ? es1 * iv1
                 : (lane == 2) ? es2 * iv2 : es3 * iv3;
        g_coef[b * NH + lane] = cf;
    }
}

// ---------------------------------------------------------------------------
// k_out: EXACT R10/R14 configuration (frozen).
// ---------------------------------------------------------------------------
__global__ void __launch_bounds__(256) k_out(const float* __restrict__ vb,
                                             float* __restrict__ out) {
    extern __shared__ float sm[];
    ulonglong2* t4     = (ulonglong2*)sm;          // [64][65]
    float*      coef_s = sm + 64 * 65 * 4;

    const int h   = blockIdx.y;
    const int b0  = blockIdx.x * 64;
    const int tid = threadIdx.x;

#pragma unroll
    for (int s = 0; s < 16; s++) {
        int i = tid + s * 256;
        int row = i >> 6, c = i & 63;
        t4[row * 65 + c] = ((const ulonglong2*)g_t)[((size_t)(b0 + row) * NH + h) * 64 + c];
    }
    if (tid < 64) coef_s[tid] = g_coef[(b0 + tid) * NH + h];
    __syncthreads();

    const int dq = tid & 15;
    const int bq = tid >> 4;

    const float4* wp = (const float4*)g_wt + (size_t)h * 64 * 64;

    unsigned long long accx[4][4], accy[4][4];
#pragma unroll
    for (int di = 0; di < 4; di++)
#pragma unroll
        for (int k = 0; k < 4; k++) { accx[di][k] = 0ull; accy[di][k] = 0ull; }

#pragma unroll 2
    for (int j4 = 0; j4 < 64; j4++) {
        ulonglong2 w[4], t[4];
#pragma unroll
        for (int di = 0; di < 4; di++) {
            float4 v = wp[j4 * 64 + dq + 16 * di];
            w[di] = *(ulonglong2*)&v;
        }
#pragma unroll
        for (int k = 0; k < 4; k++) t[k] = t4[(bq + 16 * k) * 65 + j4];
#pragma unroll
        for (int di = 0; di < 4; di++)
#pragma unroll
            for (int k = 0; k < 4; k++) {
                accx[di][k] = f2fma(w[di].x, t[k].x, accx[di][k]);
                accy[di][k] = f2fma(w[di].y, t[k].y, accy[di][k]);
            }
    }

    float bv[4];
#pragma unroll
    for (int di = 0; di < 4; di++) bv[di] = vb[h * 64 + dq + 16 * di];

#pragma unroll
    for (int k = 0; k < 4; k++) {
        int bb = bq + 16 * k;
        float cf = coef_s[bb];
        float* op = out + (size_t)(b0 + bb) * DIMM + h * 64;
#pragma unroll
        for (int di = 0; di < 4; di++) {
            float r = (f2lo(accx[di][k]) + f2hi(accx[di][k]))
                    + (f2lo(accy[di][k]) + f2hi(accy[di][k]));
            op[dq + 16 * di] = fmaf(cf, bv[di], r);
        }
    }
}

// ---------------------------------------------------------------------------
extern "C" void kernel_launch(void* const* d_in, const int* in_sizes, int n_in,
                              void* d_out, int out_size) {
    const float* x     = (const float*)d_in[0];
    const int*   batch = (const int*)d_in[1];
    const float* q     = (const float*)d_in[2];
    const float* kw    = (const float*)d_in[3];
    const float* kb    = (const float*)d_in[4];
    const float* vw    = (const float*)d_in[5];
    const float* vb    = (const float*)d_in[6];
    float*       out   = (float*)d_out;

    const int smem_main = 8 * RG * 128 * 16;          // 98304 -> 2 blocks/SM (= reg cap)
    const int smem_out  = 64 * 65 * 16 + 64 * 4;      // 66816
    cudaFuncSetAttribute(k_main, cudaFuncAttributeMaxDynamicSharedMemorySize, smem_main);
    cudaFuncSetAttribute(k_out,  cudaFuncAttributeMaxDynamicSharedMemorySize, smem_out);

    k_prep<<<NN / 256 + 1 + 256, 256>>>(batch, q, kw, kb, vw);
    k_main<<<BSEG / 8, 256, smem_main>>>(x);
    k_out<<<dim3(BSEG / 64, NH), 256, smem_out>>>(vb, out);
}

// round 17
// speedup vs baseline: 1.2859x; 1.2859x over previous
#include <cuda_runtime.h>
#include <math.h>

#define NN   262144
#define DIMM 256
#define NH   4
#define HD   64
#define BSEG 4096
#define SCALE 0.125f
#define EPSV 1e-8f
#define RG   6      // k_main ring slots per warp (slot = 2 rows = 2KB); prefetch 5

// ---- device scratch ----
__device__ float g_wtil[NH * DIMM];
__device__ float g_ctil[NH];
__device__ int   g_segstart[BSEG + 1];
__device__ float g_t[BSEG * NH * DIMM];      // normalized weighted sums t~
__device__ float g_coef[BSEG * NH];          // esum/(esum+eps)
__device__ float g_wt[NH * 64 * 64 * 4];     // vw transposed: [h][j4][d][jj]

// ---- packed f32x2 helpers ----
__device__ __forceinline__ unsigned long long f2mul(unsigned long long a, unsigned long long b) {
    unsigned long long r; asm("mul.rn.f32x2 %0,%1,%2;" : "=l"(r) : "l"(a), "l"(b)); return r;
}
__device__ __forceinline__ unsigned long long f2fma(unsigned long long a, unsigned long long b,
                                                    unsigned long long c) {
    unsigned long long r; asm("fma.rn.f32x2 %0,%1,%2,%3;" : "=l"(r) : "l"(a), "l"(b), "l"(c)); return r;
}
__device__ __forceinline__ unsigned long long fpack(float a, float b) {
    unsigned long long r; asm("mov.b64 %0,{%1,%2};" : "=l"(r) : "f"(a), "f"(b)); return r;
}
__device__ __forceinline__ float f2lo(unsigned long long a) { float2 p = *(float2*)&a; return p.x; }
__device__ __forceinline__ float f2hi(unsigned long long a) { float2 p = *(float2*)&a; return p.y; }

__device__ __forceinline__ void cpa16(void* dst_smem, const void* src) {
    unsigned u = (unsigned)__cvta_generic_to_shared(dst_smem);
    asm volatile("cp.async.cg.shared.global [%0], [%1], 16;" :: "r"(u), "l"(src) : "memory");
}
#define CP_COMMIT() asm volatile("cp.async.commit_group;" ::: "memory")
#define CP_WAIT(n)  asm volatile("cp.async.wait_group %0;" :: "n"(n) : "memory")

// ---------------------------------------------------------------------------
// k_prep: ONE launch, fold PARALLELIZED over 4 head-blocks (fixes the R16
// single-block 39.6us straggler).
//   blocks [0,1024):     segment boundaries
//   blocks [1024,1028):  fold key weights, head h = bx-1024 (R14 k_fold body)
//   blocks [1028,1284):  transpose vw
// ---------------------------------------------------------------------------
__global__ void k_prep(const int* __restrict__ batch,
                       const float* __restrict__ q,
                       const float* __restrict__ kw,
                       const float* __restrict__ kb,
                       const float* __restrict__ vw) {
    const int bx = blockIdx.x;
    if (bx < NN / 256) {
        int i = bx * 256 + threadIdx.x;
        int cur  = batch[i];
        int prev = (i == 0) ? -1 : batch[i - 1];
        for (int b = prev + 1; b <= cur; b++) g_segstart[b] = i;
        if (i == NN - 1)
            for (int b = cur + 1; b <= BSEG; b++) g_segstart[b] = NN;
    } else if (bx < NN / 256 + NH) {
        int h = bx - NN / 256;
        int j = threadIdx.x;
        float acc = 0.f;
#pragma unroll 8
        for (int d = 0; d < HD; d++)
            acc = fmaf(q[h * HD + d], kw[(h * HD + d) * DIMM + j], acc);
        g_wtil[h * DIMM + j] = acc * SCALE;
        if (j == 0) {
            float c = 0.f;
#pragma unroll 8
            for (int d = 0; d < HD; d++)
                c = fmaf(q[h * HD + d], kb[h * HD + d], c);
            g_ctil[h] = c * SCALE;
        }
    } else {
        int i = (bx - NN / 256 - NH) * 256 + threadIdx.x;
        int row = i >> 8, j = i & 255;
        int h = row >> 6, d = row & 63;
        g_wt[((h * 64 + (j >> 2)) * 64 + d) * 4 + (j & 3)] = vw[i];
    }
}

// ---------------------------------------------------------------------------
// k_main: R16 configuration VERBATIM (measured ~48us by subtraction):
// weights in registers, RG=6 ring, prefetch 5 (10KB in flight per warp).
// ---------------------------------------------------------------------------
__device__ __forceinline__ void process_pair(
    ulonglong2 v0, ulonglong2 v1, ulonglong2 u0, ulonglong2 u1,
    bool row1ok, int lane, float ctv,
    const ulonglong2 (&w0)[NH], const ulonglong2 (&w1)[NH],
    ulonglong2 (&accA)[NH], ulonglong2 (&accB)[NH], float& es)
{
    float a[8];
#pragma unroll
    for (int h = 0; h < NH; h++) {
        unsigned long long p;
        p = f2mul(v0.x, w0[h].x); p = f2fma(v0.y, w0[h].y, p);
        p = f2fma(v1.x, w1[h].x, p); p = f2fma(v1.y, w1[h].y, p);
        a[h] = f2lo(p) + f2hi(p);
        p = f2mul(u0.x, w0[h].x); p = f2fma(u0.y, w0[h].y, p);
        p = f2fma(u1.x, w1[h].x, p); p = f2fma(u1.y, w1[h].y, p);
        a[4 + h] = f2lo(p) + f2hi(p);
    }
    const bool b4 = (lane & 16) != 0;
#pragma unroll
    for (int i = 0; i < 4; i++) {
        float mine = b4 ? a[i + 4] : a[i];
        float oth  = b4 ? a[i]     : a[i + 4];
        oth = __shfl_xor_sync(0xffffffffu, oth, 16);
        a[i] = mine + oth;
    }
    const bool b3 = (lane & 8) != 0;
#pragma unroll
    for (int i = 0; i < 2; i++) {
        float mine = b3 ? a[i + 2] : a[i];
        float oth  = b3 ? a[i]     : a[i + 2];
        oth = __shfl_xor_sync(0xffffffffu, oth, 8);
        a[i] = mine + oth;
    }
    const bool b2 = (lane & 4) != 0;
    float mine = b2 ? a[1] : a[0];
    float oth  = b2 ? a[0] : a[1];
    oth = __shfl_xor_sync(0xffffffffu, oth, 4);
    float c = mine + oth;
    c += __shfl_xor_sync(0xffffffffu, c, 2);
    c += __shfl_xor_sync(0xffffffffu, c, 1);

    float e = __expf(c + ctv);            // lane's item: r=(lane>>4)&1, h=(lane>>2)&3
    if (lane >= 16 && !row1ok) e = 0.f;   // zero padded row
    if ((lane & 3) == 0) es += e;         // one accumulator lane per item

    float e00 = __shfl_sync(0xffffffffu, e, 0);
    float e01 = __shfl_sync(0xffffffffu, e, 4);
    float e02 = __shfl_sync(0xffffffffu, e, 8);
    float e03 = __shfl_sync(0xffffffffu, e, 12);
    float e10 = __shfl_sync(0xffffffffu, e, 16);
    float e11 = __shfl_sync(0xffffffffu, e, 20);
    float e12 = __shfl_sync(0xffffffffu, e, 24);
    float e13 = __shfl_sync(0xffffffffu, e, 28);

    unsigned long long k0 = fpack(e00, e00), k1 = fpack(e01, e01);
    unsigned long long k2 = fpack(e02, e02), k3 = fpack(e03, e03);
    unsigned long long m0 = fpack(e10, e10), m1 = fpack(e11, e11);
    unsigned long long m2 = fpack(e12, e12), m3 = fpack(e13, e13);

    accA[0].x = f2fma(k0, v0.x, accA[0].x); accA[0].y = f2fma(k0, v0.y, accA[0].y);
    accB[0].x = f2fma(k0, v1.x, accB[0].x); accB[0].y = f2fma(k0, v1.y, accB[0].y);
    accA[1].x = f2fma(k1, v0.x, accA[1].x); accA[1].y = f2fma(k1, v0.y, accA[1].y);
    accB[1].x = f2fma(k1, v1.x, accB[1].x); accB[1].y = f2fma(k1, v1.y, accB[1].y);
    accA[2].x = f2fma(k2, v0.x, accA[2].x); accA[2].y = f2fma(k2, v0.y, accA[2].y);
    accB[2].x = f2fma(k2, v1.x, accB[2].x); accB[2].y = f2fma(k2, v1.y, accB[2].y);
    accA[3].x = f2fma(k3, v0.x, accA[3].x); accA[3].y = f2fma(k3, v0.y, accA[3].y);
    accB[3].x = f2fma(k3, v1.x, accB[3].x); accB[3].y = f2fma(k3, v1.y, accB[3].y);

    accA[0].x = f2fma(m0, u0.x, accA[0].x); accA[0].y = f2fma(m0, u0.y, accA[0].y);
    accB[0].x = f2fma(m0, u1.x, accB[0].x); accB[0].y = f2fma(m0, u1.y, accB[0].y);
    accA[1].x = f2fma(m1, u0.x, accA[1].x); accA[1].y = f2fma(m1, u0.y, accA[1].y);
    accB[1].x = f2fma(m1, u1.x, accB[1].x); accB[1].y = f2fma(m1, u1.y, accB[1].y);
    accA[2].x = f2fma(m2, u0.x, accA[2].x); accA[2].y = f2fma(m2, u0.y, accA[2].y);
    accB[2].x = f2fma(m2, u1.x, accB[2].x); accB[2].y = f2fma(m2, u1.y, accB[2].y);
    accA[3].x = f2fma(m3, u0.x, accA[3].x); accA[3].y = f2fma(m3, u0.y, accA[3].y);
    accB[3].x = f2fma(m3, u1.x, accB[3].x); accB[3].y = f2fma(m3, u1.y, accB[3].y);
}

__global__ void __launch_bounds__(256) k_main(const float* __restrict__ x) {
    extern __shared__ float4 ring_all[];
    const int lane = threadIdx.x & 31;
    const int wid  = threadIdx.x >> 5;
    const int b    = blockIdx.x * 8 + wid;
    float4* ring = ring_all + wid * (RG * 128);

    const int s0  = g_segstart[b];
    const int s1  = g_segstart[b + 1];
    const int cnt = s1 - s0;
    const int ng  = (cnt + 1) >> 1;

    const float4* wt4 = (const float4*)g_wtil;
    ulonglong2 w0[NH], w1[NH];
#pragma unroll
    for (int h = 0; h < NH; h++) {
        float4 t = wt4[h * 64 + lane];      w0[h] = *(ulonglong2*)&t;
        float4 u = wt4[h * 64 + 32 + lane]; w1[h] = *(ulonglong2*)&u;
    }
    const float ctv = g_ctil[(lane >> 2) & 3];

    ulonglong2 accA[NH], accB[NH];
#pragma unroll
    for (int h = 0; h < NH; h++) { accA[h].x = accA[h].y = 0ull; accB[h].x = accB[h].y = 0ull; }
    float es = 0.f;

    const float4* xp = (const float4*)x;

#define ISSUE(G) do {                                             \
        int slot_ = (G) % RG;                                     \
        int r0_ = s0 + 2 * (G);                                   \
        int r1_ = (2 * (G) + 1 < cnt) ? r0_ + 1 : r0_;            \
        float4* d_ = ring + slot_ * 128;                          \
        cpa16(d_ + lane,      xp + (size_t)r0_ * 64 + lane);      \
        cpa16(d_ + 32 + lane, xp + (size_t)r0_ * 64 + 32 + lane); \
        cpa16(d_ + 64 + lane, xp + (size_t)r1_ * 64 + lane);      \
        cpa16(d_ + 96 + lane, xp + (size_t)r1_ * 64 + 32 + lane); \
    } while (0)

#pragma unroll
    for (int p = 0; p < 5; p++) { if (p < ng) ISSUE(p); CP_COMMIT(); }

    for (int g = 0; g < ng; g++) {
        if (g + 5 < ng) ISSUE(g + 5);
        CP_COMMIT();
        CP_WAIT(5);
        const float4* sl = ring + (g % RG) * 128;
        float4 f0 = sl[lane], f1 = sl[32 + lane];
        float4 f2v = sl[64 + lane], f3 = sl[96 + lane];
        process_pair(*(ulonglong2*)&f0, *(ulonglong2*)&f1,
                     *(ulonglong2*)&f2v, *(ulonglong2*)&f3,
                     (2 * g + 1) < cnt, lane, ctv, w0, w1, accA, accB, es);
    }
#undef ISSUE

    // es: lane 4h (r0) + lane 4h+16 (r1) -> esum[h] at lane 4h
    es += __shfl_xor_sync(0xffffffffu, es, 16);
    float es0 = __shfl_sync(0xffffffffu, es, 0);
    float es1 = __shfl_sync(0xffffffffu, es, 4);
    float es2 = __shfl_sync(0xffffffffu, es, 8);
    float es3 = __shfl_sync(0xffffffffu, es, 12);

    float iv0 = 1.0f / (es0 + EPSV), iv1 = 1.0f / (es1 + EPSV);
    float iv2 = 1.0f / (es2 + EPSV), iv3 = 1.0f / (es3 + EPSV);
    unsigned long long ii[NH] = { fpack(iv0, iv0), fpack(iv1, iv1),
                                  fpack(iv2, iv2), fpack(iv3, iv3) };
    float4* tp = (float4*)(g_t + (size_t)b * NH * DIMM);
#pragma unroll
    for (int h = 0; h < NH; h++) {
        ulonglong2 sa, sb;
        sa.x = f2mul(ii[h], accA[h].x); sa.y = f2mul(ii[h], accA[h].y);
        sb.x = f2mul(ii[h], accB[h].x); sb.y = f2mul(ii[h], accB[h].y);
        tp[h * 64 + lane]      = *(float4*)&sa;
        tp[h * 64 + 32 + lane] = *(float4*)&sb;
    }
    if (lane < NH) {
        float cf = (lane == 0) ? es0 * iv0 : (lane == 1) ? es1 * iv1
                 : (lane == 2) ? es2 * iv2 : es3 * iv3;
        g_coef[b * NH + lane] = cf;
    }
}

// ---------------------------------------------------------------------------
// k_out: EXACT R10/R14 configuration (frozen).
// ---------------------------------------------------------------------------
__global__ void __launch_bounds__(256) k_out(const float* __restrict__ vb,
                                             float* __restrict__ out) {
    extern __shared__ float sm[];
    ulonglong2* t4     = (ulonglong2*)sm;          // [64][65]
    float*      coef_s = sm + 64 * 65 * 4;

    const int h   = blockIdx.y;
    const int b0  = blockIdx.x * 64;
    const int tid = threadIdx.x;

#pragma unroll
    for (int s = 0; s < 16; s++) {
        int i = tid + s * 256;
        int row = i >> 6, c = i & 63;
        t4[row * 65 + c] = ((const ulonglong2*)g_t)[((size_t)(b0 + row) * NH + h) * 64 + c];
    }
    if (tid < 64) coef_s[tid] = g_coef[(b0 + tid) * NH + h];
    __syncthreads();

    const int dq = tid & 15;
    const int bq = tid >> 4;

    const float4* wp = (const float4*)g_wt + (size_t)h * 64 * 64;

    unsigned long long accx[4][4], accy[4][4];
#pragma unroll
    for (int di = 0; di < 4; di++)
#pragma unroll
        for (int k = 0; k < 4; k++) { accx[di][k] = 0ull; accy[di][k] = 0ull; }

#pragma unroll 2
    for (int j4 = 0; j4 < 64; j4++) {
        ulonglong2 w[4], t[4];
#pragma unroll
        for (int di = 0; di < 4; di++) {
            float4 v = wp[j4 * 64 + dq + 16 * di];
            w[di] = *(ulonglong2*)&v;
        }
#pragma unroll
        for (int k = 0; k < 4; k++) t[k] = t4[(bq + 16 * k) * 65 + j4];
#pragma unroll
        for (int di = 0; di < 4; di++)
#pragma unroll
            for (int k = 0; k < 4; k++) {
                accx[di][k] = f2fma(w[di].x, t[k].x, accx[di][k]);
                accy[di][k] = f2fma(w[di].y, t[k].y, accy[di][k]);
            }
    }

    float bv[4];
#pragma unroll
    for (int di = 0; di < 4; di++) bv[di] = vb[h * 64 + dq + 16 * di];

#pragma unroll
    for (int k = 0; k < 4; k++) {
        int bb = bq + 16 * k;
        float cf = coef_s[bb];
        float* op = out + (size_t)(b0 + bb) * DIMM + h * 64;
#pragma unroll
        for (int di = 0; di < 4; di++) {
            float r = (f2lo(accx[di][k]) + f2hi(accx[di][k]))
                    + (f2lo(accy[di][k]) + f2hi(accy[di][k]));
            op[dq + 16 * di] = fmaf(cf, bv[di], r);
        }
    }
}

// ---------------------------------------------------------------------------
extern "C" void kernel_launch(void* const* d_in, const int* in_sizes, int n_in,
                              void* d_out, int out_size) {
    const float* x     = (const float*)d_in[0];
    const int*   batch = (const int*)d_in[1];
    const float* q     = (const float*)d_in[2];
    const float* kw    = (const float*)d_in[3];
    const float* kb    = (const float*)d_in[4];
    const float* vw    = (const float*)d_in[5];
    const float* vb    = (const float*)d_in[6];
    float*       out   = (float*)d_out;

    const int smem_main = 8 * RG * 128 * 16;          // 98304 -> 2 blocks/SM (= reg cap)
    const int smem_out  = 64 * 65 * 16 + 64 * 4;      // 66816
    cudaFuncSetAttribute(k_main, cudaFuncAttributeMaxDynamicSharedMemorySize, smem_main);
    cudaFuncSetAttribute(k_out,  cudaFuncAttributeMaxDynamicSharedMemorySize, smem_out);

    k_prep<<<NN / 256 + NH + 256, 256>>>(batch, q, kw, kb, vw);
    k_main<<<BSEG / 8, 256, smem_main>>>(x);
    k_out<<<dim3(BSEG / 64, NH), 256, smem_out>>>(vb, out);
}